// round 5
// baseline (speedup 1.0000x reference)
#include <cuda_runtime.h>

#define NB 64
#define NN 512
#define NF 64

// Scratch (device globals; no allocation allowed in kernel_launch)
__device__ float g_XW[NB * NN * NF];   // 8 MB
__device__ float g_P [NB * NN * NF];   // 8 MB
__device__ float g_r [NB * NN];        // 128 KB
__device__ float g_cs[NF];
__device__ int   g_N [NB];

// ---------------- f32x2 helpers ----------------
typedef unsigned long long u64;

__device__ __forceinline__ u64 dup2(float x) {
    unsigned xi = __float_as_uint(x);
    u64 d;
    asm("mov.b64 %0, {%1, %1};" : "=l"(d) : "r"(xi));
    return d;
}
__device__ __forceinline__ u64 pack2(float lo, float hi) {
    unsigned a = __float_as_uint(lo), b = __float_as_uint(hi);
    u64 d;
    asm("mov.b64 %0, {%1, %2};" : "=l"(d) : "r"(a), "r"(b));
    return d;
}
__device__ __forceinline__ void unpack2(u64 d, float& lo, float& hi) {
    unsigned a, b;
    asm("mov.b64 {%0, %1}, %2;" : "=r"(a), "=r"(b) : "l"(d));
    lo = __uint_as_float(a);
    hi = __uint_as_float(b);
}
#define FMA2(acc, a, b) \
    asm("fma.rn.f32x2 %0, %1, %2, %0;" : "+l"(acc) : "l"(a), "l"(b))

__device__ __forceinline__ float tanh_fast(float x) {
    float y;
    asm("tanh.approx.f32 %0, %1;" : "=f"(y) : "f"(x));
    return y;
}

// ---------------------------------------------------------------------------
// col_sum[f] = sum_i a[i][f]; also decode N robustly (int32 vs int64 storage).
__global__ void k_colsum(const float* __restrict__ a, const int* __restrict__ N32) {
    const int f = threadIdx.x;  // 64 threads
    float s = 0.f;
#pragma unroll
    for (int i = 0; i < NF; i++) s += a[i * NF + f];
    g_cs[f] = s;

    __shared__ int odd_nz;
    if (f == 0) odd_nz = 0;
    __syncthreads();
    if (f < 32 && N32[2 * f + 1] != 0) atomicOr(&odd_nz, 1);
    __syncthreads();
    g_N[f] = odd_nz ? N32[f] : N32[2 * f];
}

// ---------------------------------------------------------------------------
// XW[r][d] = sum_c X[r][c] * W[c][d]   (small: 0.13 GF)
__global__ __launch_bounds__(256) void k_xw(const float* __restrict__ X,
                                            const float* __restrict__ W) {
    __shared__ __align__(16) float Ws[NF][NF];
    __shared__ __align__(16) float Xs[64][NF + 4];
    const int r0 = blockIdx.x * 64;
    const int t = threadIdx.x;
    for (int i = t; i < NF * NF; i += 256) Ws[i / NF][i % NF] = W[i];
    for (int i = t; i < 64 * NF; i += 256)
        Xs[i / NF][i % NF] = X[(size_t)(r0 + i / NF) * NF + (i % NF)];
    __syncthreads();
    const int tx = t & 15, ty = t >> 4;
    float acc[4][4] = {};
    for (int c = 0; c < NF; c++) {
        float xv[4], wv[4];
#pragma unroll
        for (int ii = 0; ii < 4; ii++) xv[ii] = Xs[ty * 4 + ii][c];
#pragma unroll
        for (int jj = 0; jj < 4; jj++) wv[jj] = Ws[c][tx * 4 + jj];
#pragma unroll
        for (int ii = 0; ii < 4; ii++)
#pragma unroll
            for (int jj = 0; jj < 4; jj++) acc[ii][jj] += xv[ii] * wv[jj];
    }
#pragma unroll
    for (int ii = 0; ii < 4; ii++)
#pragma unroll
        for (int jj = 0; jj < 4; jj++)
            g_XW[(size_t)(r0 + ty * 4 + ii) * NF + tx * 4 + jj] = acc[ii][jj];
}

// ---------------------------------------------------------------------------
// P[b][i][f] = sum_j A[b][i][j]*Y[j][f] + (i<N[b] ? Y[i][f] : 0),  Y = XW*cs
// r[b][i]    = sum_j A[b][i][j] + (i<N[b] ? 1 : 0)
// 64x64 tile per block, f32x2 inner, all smem reads LDS.128.
__global__ __launch_bounds__(256) void k_p(const float* __restrict__ Ag) {
    const int b = blockIdx.y;
    const int i0 = blockIdx.x * 64;
    __shared__ __align__(16) float AsT[64][68];  // AsT[j][i]
    __shared__ __align__(16) float Ys [64][68];  // Ys[j][f] (already *cs)
    __shared__ __align__(16) float csv[NF];
    const int t = threadIdx.x;
    const int tx = t & 15, ty = t >> 4;
    if (t < NF) csv[t] = g_cs[t];
    __syncthreads();

    const float*  Ab   = Ag + (size_t)b * NN * NN;
    const float4* XWb4 = (const float4*)(g_XW + (size_t)b * NN * NF);

    u64 acc2[4][2] = {};
    float rsum = 0.f;

    for (int j0 = 0; j0 < NN; j0 += 64) {
        __syncthreads();
        // A tile -> AsT (transposed), coalesced float4 global reads
        for (int q = t; q < 64 * 16; q += 256) {
            int r = q >> 4, c4 = q & 15;
            float4 v = *(const float4*)&Ab[(size_t)(i0 + r) * NN + j0 + c4 * 4];
            AsT[c4 * 4 + 0][r] = v.x;
            AsT[c4 * 4 + 1][r] = v.y;
            AsT[c4 * 4 + 2][r] = v.z;
            AsT[c4 * 4 + 3][r] = v.w;
        }
        // Y tile = XW*cs, row-major float4
        for (int q = t; q < 64 * 16; q += 256) {
            int j = q >> 4, f4 = q & 15;
            float4 v = XWb4[(size_t)(j0 + j) * 16 + f4];
            float4 c = *(const float4*)&csv[f4 * 4];
            v.x *= c.x; v.y *= c.y; v.z *= c.z; v.w *= c.w;
            *(float4*)&Ys[j][f4 * 4] = v;
        }
        __syncthreads();

        if (t < 64) {
#pragma unroll 8
            for (int jj = 0; jj < 64; jj++) rsum += AsT[jj][t];
        }

#pragma unroll 8
        for (int jj = 0; jj < 64; jj++) {
            float4 av = *(float4*)&AsT[jj][ty * 4];
            float4 yv = *(float4*)&Ys[jj][tx * 4];
            u64 y01 = pack2(yv.x, yv.y);
            u64 y23 = pack2(yv.z, yv.w);
            u64 a0 = dup2(av.x), a1 = dup2(av.y), a2 = dup2(av.z), a3 = dup2(av.w);
            FMA2(acc2[0][0], a0, y01); FMA2(acc2[0][1], a0, y23);
            FMA2(acc2[1][0], a1, y01); FMA2(acc2[1][1], a1, y23);
            FMA2(acc2[2][0], a2, y01); FMA2(acc2[2][1], a2, y23);
            FMA2(acc2[3][0], a3, y01); FMA2(acc2[3][1], a3, y23);
        }
    }

    const int nb = g_N[b];
    const float4 c4v = *(const float4*)&csv[tx * 4];
#pragma unroll
    for (int ii = 0; ii < 4; ii++) {
        const int i = i0 + ty * 4 + ii;
        float4 o;
        unpack2(acc2[ii][0], o.x, o.y);
        unpack2(acc2[ii][1], o.z, o.w);
        if (i < nb) {
            float4 xw = XWb4[(size_t)i * 16 + tx];
            o.x += xw.x * c4v.x; o.y += xw.y * c4v.y;
            o.z += xw.z * c4v.z; o.w += xw.w * c4v.w;
        }
        *(float4*)&g_P[((size_t)b * NN + i) * NF + tx * 4] = o;
    }
    if (t < 64) {
        const int i = i0 + t;
        g_r[b * NN + i] = rsum + ((i < nb) ? 1.0f : 0.0f);
    }
}

// ---------------------------------------------------------------------------
// k_fused: H[i][d] = sum_k tanh(P[i,:].XW[k,:] + r[i]*ba[k]) * XW[k][d] + bW[d]
// i-tile = 128, 256 threads, 8x4 thread tile, f32x2 + LDS.128 everywhere.
#define IT 128
// dynamic smem layout (floats):
#define OFF_PST  0                         // PsT[64][IT+4]
#define OFF_XWS  (OFF_PST + 64 * (IT + 4)) // XWs[64][68]
#define OFF_XWT  (OFF_XWS + 64 * 68)       // XWT[64][68]
#define OFF_SST  (OFF_XWT + 64 * 68)       // SsT[64][IT+4]
#define OFF_RS   (OFF_SST + 64 * (IT + 4)) // rs[IT]
#define OFF_BAK  (OFF_RS + IT)             // bak[64]
#define SMEM_FLT (OFF_BAK + 64)

__global__ __launch_bounds__(256, 2) void k_fused(const float* __restrict__ bias_a,
                                                  const float* __restrict__ bias_W,
                                                  float* __restrict__ H) {
    extern __shared__ __align__(16) float dsm[];
    float* PsT = dsm + OFF_PST;   // [f][i], stride IT+4
    float* XWs = dsm + OFF_XWS;   // [k][d], stride 68
    float* XWT = dsm + OFF_XWT;   // [f][k], stride 68
    float* SsT = dsm + OFF_SST;   // [k][i], stride IT+4
    float* rs  = dsm + OFF_RS;
    float* bak = dsm + OFF_BAK;
    const int PST = IT + 4;

    const int b  = blockIdx.y;
    const int i0 = blockIdx.x * IT;
    const int t  = threadIdx.x;
    const int tx = t & 15, ty = t >> 4;  // tx*4 = col, ty*8 = row

    const float4* Pb4  = (const float4*)(g_P  + ((size_t)b * NN + i0) * NF);
    const float4* XWb4 = (const float4*)(g_XW + (size_t)b * NN * NF);

    // Load P tile transposed
    for (int q = t; q < IT * 16; q += 256) {
        int i = q >> 4, f4 = q & 15;
        float4 v = Pb4[i * 16 + f4];
        PsT[(f4 * 4 + 0) * PST + i] = v.x;
        PsT[(f4 * 4 + 1) * PST + i] = v.y;
        PsT[(f4 * 4 + 2) * PST + i] = v.z;
        PsT[(f4 * 4 + 3) * PST + i] = v.w;
    }
    if (t < IT) rs[t] = g_r[b * NN + i0 + t];

    u64 hacc2[8][2] = {};
    float rv[8];

    for (int k0 = 0; k0 < NN; k0 += 64) {
        __syncthreads();  // prev-iter consumers done; also fences initial loads
        for (int q = t; q < 64 * 16; q += 256) {
            int k = q >> 4, f4 = q & 15;
            float4 v = XWb4[(size_t)(k0 + k) * 16 + f4];
            *(float4*)&XWs[k * 68 + f4 * 4] = v;
            XWT[(f4 * 4 + 0) * 68 + k] = v.x;
            XWT[(f4 * 4 + 1) * 68 + k] = v.y;
            XWT[(f4 * 4 + 2) * 68 + k] = v.z;
            XWT[(f4 * 4 + 3) * 68 + k] = v.w;
        }
        if (t < 64) bak[t] = bias_a[k0 + t];
        __syncthreads();

        // ---- S = tanh(P @ XW^T + r*ba), stored transposed SsT[k][i] ----
        u64 sacc2[8][2] = {};
#pragma unroll 8
        for (int f = 0; f < NF; f++) {
            float4 p0 = *(float4*)&PsT[f * PST + ty * 8];
            float4 p1 = *(float4*)&PsT[f * PST + ty * 8 + 4];
            float4 xv = *(float4*)&XWT[f * 68 + tx * 4];
            u64 x01 = pack2(xv.x, xv.y);
            u64 x23 = pack2(xv.z, xv.w);
            u64 d0 = dup2(p0.x), d1 = dup2(p0.y), d2 = dup2(p0.z), d3 = dup2(p0.w);
            u64 d4 = dup2(p1.x), d5 = dup2(p1.y), d6 = dup2(p1.z), d7 = dup2(p1.w);
            FMA2(sacc2[0][0], d0, x01); FMA2(sacc2[0][1], d0, x23);
            FMA2(sacc2[1][0], d1, x01); FMA2(sacc2[1][1], d1, x23);
            FMA2(sacc2[2][0], d2, x01); FMA2(sacc2[2][1], d2, x23);
            FMA2(sacc2[3][0], d3, x01); FMA2(sacc2[3][1], d3, x23);
            FMA2(sacc2[4][0], d4, x01); FMA2(sacc2[4][1], d4, x23);
            FMA2(sacc2[5][0], d5, x01); FMA2(sacc2[5][1], d5, x23);
            FMA2(sacc2[6][0], d6, x01); FMA2(sacc2[6][1], d6, x23);
            FMA2(sacc2[7][0], d7, x01); FMA2(sacc2[7][1], d7, x23);
        }
        float s[8][4];
#pragma unroll
        for (int ii = 0; ii < 8; ii++) {
            unpack2(sacc2[ii][0], s[ii][0], s[ii][1]);
            unpack2(sacc2[ii][1], s[ii][2], s[ii][3]);
        }
#pragma unroll
        for (int ii = 0; ii < 8; ii++) rv[ii] = rs[ty * 8 + ii];
#pragma unroll
        for (int kk = 0; kk < 4; kk++) {
            const int k = tx * 4 + kk;
            const float bv = bak[k];
            float4 w0, w1;
            w0.x = tanh_fast(s[0][kk] + rv[0] * bv);
            w0.y = tanh_fast(s[1][kk] + rv[1] * bv);
            w0.z = tanh_fast(s[2][kk] + rv[2] * bv);
            w0.w = tanh_fast(s[3][kk] + rv[3] * bv);
            w1.x = tanh_fast(s[4][kk] + rv[4] * bv);
            w1.y = tanh_fast(s[5][kk] + rv[5] * bv);
            w1.z = tanh_fast(s[6][kk] + rv[6] * bv);
            w1.w = tanh_fast(s[7][kk] + rv[7] * bv);
            *(float4*)&SsT[k * PST + ty * 8]     = w0;
            *(float4*)&SsT[k * PST + ty * 8 + 4] = w1;
        }
        __syncthreads();

        // ---- H += S @ XW ----
#pragma unroll 8
        for (int kk = 0; kk < 64; kk++) {
            float4 s0 = *(float4*)&SsT[kk * PST + ty * 8];
            float4 s1 = *(float4*)&SsT[kk * PST + ty * 8 + 4];
            float4 xv = *(float4*)&XWs[kk * 68 + tx * 4];
            u64 x01 = pack2(xv.x, xv.y);
            u64 x23 = pack2(xv.z, xv.w);
            u64 d0 = dup2(s0.x), d1 = dup2(s0.y), d2 = dup2(s0.z), d3 = dup2(s0.w);
            u64 d4 = dup2(s1.x), d5 = dup2(s1.y), d6 = dup2(s1.z), d7 = dup2(s1.w);
            FMA2(hacc2[0][0], d0, x01); FMA2(hacc2[0][1], d0, x23);
            FMA2(hacc2[1][0], d1, x01); FMA2(hacc2[1][1], d1, x23);
            FMA2(hacc2[2][0], d2, x01); FMA2(hacc2[2][1], d2, x23);
            FMA2(hacc2[3][0], d3, x01); FMA2(hacc2[3][1], d3, x23);
            FMA2(hacc2[4][0], d4, x01); FMA2(hacc2[4][1], d4, x23);
            FMA2(hacc2[5][0], d5, x01); FMA2(hacc2[5][1], d5, x23);
            FMA2(hacc2[6][0], d6, x01); FMA2(hacc2[6][1], d6, x23);
            FMA2(hacc2[7][0], d7, x01); FMA2(hacc2[7][1], d7, x23);
        }
    }

    const float4 bw = *(const float4*)&bias_W[tx * 4];
#pragma unroll
    for (int ii = 0; ii < 8; ii++) {
        float4 o;
        unpack2(hacc2[ii][0], o.x, o.y);
        unpack2(hacc2[ii][1], o.z, o.w);
        o.x += bw.x; o.y += bw.y; o.z += bw.z; o.w += bw.w;
        *(float4*)&H[((size_t)b * NN + i0 + ty * 8 + ii) * NF + tx * 4] = o;
    }
}

// ---------------------------------------------------------------------------
extern "C" void kernel_launch(void* const* d_in, const int* in_sizes, int n_in,
                              void* d_out, int out_size) {
    const float* X  = (const float*)d_in[0];
    const float* A  = (const float*)d_in[1];
    const int*   N  = (const int*)d_in[2];   // robustly decoded in k_colsum
    const float* W  = (const float*)d_in[3];
    const float* a  = (const float*)d_in[4];
    const float* bW = (const float*)d_in[5];
    const float* ba = (const float*)d_in[6];
    float* H = (float*)d_out;

    cudaFuncSetAttribute(k_fused, cudaFuncAttributeMaxDynamicSharedMemorySize,
                         SMEM_FLT * (int)sizeof(float));

    k_colsum<<<1, NF>>>(a, N);
    k_xw<<<(NB * NN) / 64, 256>>>(X, W);
    k_p<<<dim3(NN / 64, NB), 256>>>(A);
    k_fused<<<dim3(NN / IT, NB), 256, SMEM_FLT * sizeof(float)>>>(ba, bW, H);
}

// round 8
// speedup vs baseline: 1.5787x; 1.5787x over previous
#include <cuda_runtime.h>
typedef unsigned int u32; typedef unsigned long long u64; typedef unsigned short u16;
#define NB 64
#define NN 512
#define NF 64

__device__ __align__(16) float g_Yrow[NB*NN*NF];     // Y=XW*cs row-major (diag adds)
__device__ __align__(16) uint4 g_Yfr [NB*64*8*32];   // [b][qj][n][lane] tf32 hi/lo frags of Y (P-gemm B)
__device__ __align__(16) uint4 g_XWfr[NB*8*8*8*32];  // [b][kt][qf][n][lane] tf32 frags of XW (S-gemm B)
__device__ __align__(16) uint4 g_XTfr[NB*8*4*8*32];  // [b][kt][qk][n][lane] bf16 frags of XW^T (H-gemm B)
__device__ float g_cs[NF];
__device__ int   g_N[NB];

__device__ __forceinline__ u32 smaddr(const void* p){
    u32 a; asm("{.reg .u64 t; cvta.to.shared.u64 t,%1; cvt.u32.u64 %0,t;}":"=r"(a):"l"(p)); return a;
}
__device__ __forceinline__ u32 t32(float x){ u32 r; asm("cvt.rna.tf32.f32 %0,%1;":"=r"(r):"f"(x)); return r; }
__device__ __forceinline__ void tsplit(float x, u32& h, u32& l){ h=t32(x); l=t32(x-__uint_as_float(h)); }
__device__ __forceinline__ u32 cvt2(float hi,float lo){ u32 r; asm("cvt.rn.bf16x2.f32 %0,%1,%2;":"=r"(r):"f"(hi),"f"(lo)); return r; }
__device__ __forceinline__ float bflo(u32 p){ return __uint_as_float(p<<16); }
__device__ __forceinline__ float bfhi(u32 p){ return __uint_as_float(p&0xFFFF0000u); }
__device__ __forceinline__ float tanhf_(float x){ float y; asm("tanh.approx.f32 %0,%1;":"=f"(y):"f"(x)); return y; }

#define MMAT(d,a,b0,b1) asm volatile( \
 "mma.sync.aligned.m16n8k8.row.col.f32.tf32.tf32.f32 {%0,%1,%2,%3},{%4,%5,%6,%7},{%8,%9},{%0,%1,%2,%3};" \
 : "+f"((d)[0]),"+f"((d)[1]),"+f"((d)[2]),"+f"((d)[3]) \
 : "r"((a)[0]),"r"((a)[1]),"r"((a)[2]),"r"((a)[3]),"r"(b0),"r"(b1))
#define MMAB(d,a,b0,b1) asm volatile( \
 "mma.sync.aligned.m16n8k16.row.col.f32.bf16.bf16.f32 {%0,%1,%2,%3},{%4,%5,%6,%7},{%8,%9},{%0,%1,%2,%3};" \
 : "+f"((d)[0]),"+f"((d)[1]),"+f"((d)[2]),"+f"((d)[3]) \
 : "r"((a)[0]),"r"((a)[1]),"r"((a)[2]),"r"((a)[3]),"r"(b0),"r"(b1))
#define CPA(dst,src) asm volatile("cp.async.cg.shared.global [%0],[%1],16;"::"r"(dst),"l"(src):"memory")
#define CPC() asm volatile("cp.async.commit_group;":::"memory")
#define CPW(n) asm volatile("cp.async.wait_group %0;"::"n"(n):"memory")

// ---------------------------------------------------------------------------
__global__ void k_colsum(const float* __restrict__ a, const int* __restrict__ N32){
    const int f=threadIdx.x; float s=0.f;
#pragma unroll
    for(int i=0;i<NF;i++) s+=a[i*NF+f];
    g_cs[f]=s;
    __shared__ int oz; if(f==0) oz=0; __syncthreads();
    if(f<32 && N32[2*f+1]!=0) atomicOr(&oz,1);
    __syncthreads();
    g_N[f]= oz ? N32[f] : N32[2*f];
}

// ---------------------------------------------------------------------------
// XW = X@W per 64-row tile; emit Yrow fp32 + fragment-packed B operands.
__global__ __launch_bounds__(256) void k_prep(const float* __restrict__ X, const float* __restrict__ W){
    __shared__ __align__(16) float Ws[64][64];
    __shared__ __align__(16) float Xs[64][68];
    __shared__ float csm[64];
    const int t=threadIdx.x, b=blockIdx.x>>3, kt=blockIdx.x&7, R0=blockIdx.x*64;
    if(t<64) csm[t]=g_cs[t];
    for(int i=t;i<64*64;i+=256) Ws[i>>6][i&63]=W[i];
    for(int i=t;i<64*64;i+=256) Xs[i>>6][i&63]=X[(size_t)(R0+(i>>6))*NF+(i&63)];
    __syncthreads();
    {
        const int tx=t&15, ty=t>>4;
        float acc[4][4]={};
        for(int c=0;c<64;c++){
            float xv[4],wv[4];
#pragma unroll
            for(int ii=0;ii<4;ii++) xv[ii]=Xs[ty*4+ii][c];
#pragma unroll
            for(int jj=0;jj<4;jj++) wv[jj]=Ws[c][tx*4+jj];
#pragma unroll
            for(int ii=0;ii<4;ii++)
#pragma unroll
                for(int jj=0;jj<4;jj++) acc[ii][jj]+=xv[ii]*wv[jj];
        }
        __syncthreads();
#pragma unroll
        for(int ii=0;ii<4;ii++)
#pragma unroll
            for(int jj=0;jj<4;jj++) Xs[ty*4+ii][tx*4+jj]=acc[ii][jj];
    }
    __syncthreads();
    const int lane=t&31, g=lane>>2, tc=lane&3;
    // Yrow fp32
#pragma unroll
    for(int u=0;u<4;u++){
        int idx=t+256*u; int r=idx>>4, f4=idx&15;
        float4 v=*(float4*)&Xs[r][f4*4];
        v.x*=csm[f4*4]; v.y*=csm[f4*4+1]; v.z*=csm[f4*4+2]; v.w*=csm[f4*4+3];
        *(float4*)&g_Yrow[(size_t)(R0+r)*NF+f4*4]=v;
    }
    // Y frags (tf32): element (j=q*8+tc(+4), f=n*8+g)
#pragma unroll
    for(int u=0;u<8;u++){
        int idx=t+256*u; int n=(idx>>5)&7, q=idx>>8;
        int f=n*8+g; float cf=csm[f];
        uint4 v;
        tsplit(Xs[q*8+tc][f]*cf,   v.x, v.y);
        tsplit(Xs[q*8+tc+4][f]*cf, v.z, v.w);
        g_Yfr[((size_t)(b*64+kt*8+q)*8+n)*32+lane]=v;
    }
    // XW frags (tf32): element (k=n*8+g, f=qf*8+tc(+4))
#pragma unroll
    for(int u=0;u<8;u++){
        int idx=t+256*u; int n=(idx>>5)&7, qf=idx>>8;
        int kr=n*8+g;
        uint4 v;
        tsplit(Xs[kr][qf*8+tc],   v.x, v.y);
        tsplit(Xs[kr][qf*8+tc+4], v.z, v.w);
        g_XWfr[(((size_t)(b*8+kt)*8+qf)*8+n)*32+lane]=v;
    }
    // XT frags (bf16 pairs): element (k=qk*16+2tc(+1,+8,+9), d=n*8+g)
#pragma unroll
    for(int u=0;u<4;u++){
        int idx=t+256*u; int n=(idx>>5)&7, qk=idx>>8;
        int d=n*8+g, k0=qk*16+2*tc;
        float x0=Xs[k0][d], x1=Xs[k0+1][d], x2=Xs[k0+8][d], x3=Xs[k0+9][d];
        uint4 v;
        v.x=cvt2(x1,x0); v.z=cvt2(x1-bfhi(v.x), x0-bflo(v.x));
        v.y=cvt2(x3,x2); v.w=cvt2(x3-bfhi(v.y), x2-bflo(v.y));
        g_XTfr[(((size_t)(b*8+kt)*4+qk)*8+n)*32+lane]=v;
    }
}

// ---------------------------------------------------------------------------
// smem map (bytes): P[0,34816) | XWf[34816,67584) | XTf[67584,83968) | rs@83968 | bas@84480
// phase-A aliases: A0[0,18432) A1[18432,36864) Yf0[36864,53248) Yf1[53248,69632)
#define SMEMB 86528
__global__ __launch_bounds__(256,2) void k_main(const float* __restrict__ A, const float* __restrict__ ba,
                                                const float* __restrict__ bW, float* __restrict__ H){
    extern __shared__ __align__(16) char sm[];
    float* Ps =(float*)sm;
    char*  XWf= sm+34816;
    char*  XTf= sm+67584;
    float* rs =(float*)(sm+83968);
    float* bas=(float*)(sm+84480);
    const int t=threadIdx.x, w=t>>5, lane=t&31, g=lane>>2, tc=lane&3;
    const int b=blockIdx.y, i0=blockIdx.x*128;
    const u32 sbase=smaddr(sm);
    bas[t]=ba[t]; bas[256+t]=ba[256+t];
    const int nb=g_N[b];
    const float* Ab = A + ((size_t)b*NN+i0)*NN;

    auto issueA=[&](int p,int it){
        const int j0=it*32;
#pragma unroll
        for(int u=0;u<4;u++){
            int idx=t+256*u; int r=idx>>3, c=idx&7;
            CPA(sbase + p*18432 + (u32)(r*36+c*4)*4, Ab + (size_t)r*NN + j0 + c*4);
        }
        const uint4* src=g_Yfr + (size_t)(b*64+it*4)*256;
#pragma unroll
        for(int u=0;u<4;u++){
            int idx=t+256*u;
            CPA(sbase + 36864 + p*16384 + (u32)idx*16, src+idx);
        }
        CPC();
    };

    // ---- phase A: pacc = A @ Y over K=512 (16 iters of 32) ----
    float pacc[8][4]={}; float rloc=0.f;
    issueA(0,0);
    for(int it=0; it<16; it++){
        const int p=it&1;
        if(it<15){ issueA(p^1,it+1); CPW(1); } else CPW(0);
        __syncthreads();
        const float* As=(const float*)(sm + p*18432);
        if(t<128){
            float s=0.f;
#pragma unroll
            for(int c=0;c<8;c++){ float4 v=*(const float4*)&As[t*36+c*4]; s+=v.x+v.y+v.z+v.w; }
            rloc+=s;
        }
        const char* Yb = sm + 36864 + p*16384;
#pragma unroll
        for(int q=0;q<4;q++){
            u32 ah[4],al[4];
            tsplit(As[(w*16+g  )*36+q*8+tc  ], ah[0],al[0]);
            tsplit(As[(w*16+g+8)*36+q*8+tc  ], ah[1],al[1]);
            tsplit(As[(w*16+g  )*36+q*8+tc+4], ah[2],al[2]);
            tsplit(As[(w*16+g+8)*36+q*8+tc+4], ah[3],al[3]);
            const uint4* yb=(const uint4*)(Yb + q*4096) + lane;
#pragma unroll
            for(int n=0;n<8;n++){
                uint4 v=yb[n*32];
                MMAT(pacc[n],ah,v.x,v.z);
                MMAT(pacc[n],ah,v.y,v.w);
                MMAT(pacc[n],al,v.x,v.z);
            }
        }
        __syncthreads();
    }
    if(t<128) rs[t]=rloc + ((i0+t)<nb ? 1.f : 0.f);

    // ---- diag add + store P to smem fp32 ----
    {
        const int il=i0+w*16+g, ih=il+8;
        const float* Yr=g_Yrow + (size_t)b*NN*NF;
#pragma unroll
        for(int n=0;n<8;n++){
            const int f=n*8+2*tc;
            if(il<nb){ pacc[n][0]+=Yr[(size_t)il*NF+f]; pacc[n][1]+=Yr[(size_t)il*NF+f+1]; }
            if(ih<nb){ pacc[n][2]+=Yr[(size_t)ih*NF+f]; pacc[n][3]+=Yr[(size_t)ih*NF+f+1]; }
            Ps[(w*16+g  )*68+f]  =pacc[n][0];
            Ps[(w*16+g  )*68+f+1]=pacc[n][1];
            Ps[(w*16+g+8)*68+f]  =pacc[n][2];
            Ps[(w*16+g+8)*68+f+1]=pacc[n][3];
        }
    }
    __syncthreads();

    // ---- phase B: S = tanh(P@XW^T + r*ba) [3xTF32]; H += S@XW [bf16 3-term] ----
    float hacc[8][4]={};
    const float rv0=rs[w*16+g], rv1=rs[w*16+g+8];
    for(int kt=0;kt<8;kt++){
        const uint4* sw=g_XWfr + (size_t)(b*8+kt)*2048;
        const uint4* st=g_XTfr + (size_t)(b*8+kt)*1024;
#pragma unroll
        for(int u=0;u<8;u++){ int idx=t+256*u; CPA(sbase+34816+(u32)idx*16, sw+idx); }
#pragma unroll
        for(int u=0;u<4;u++){ int idx=t+256*u; CPA(sbase+67584+(u32)idx*16, st+idx); }
        CPC(); CPW(0);
        __syncthreads();
        float sacc[8][4]={};
#pragma unroll
        for(int qf=0;qf<8;qf++){
            u32 ph[4],pl[4];
            tsplit(Ps[(w*16+g  )*68+qf*8+tc  ], ph[0],pl[0]);
            tsplit(Ps[(w*16+g+8)*68+qf*8+tc  ], ph[1],pl[1]);
            tsplit(Ps[(w*16+g  )*68+qf*8+tc+4], ph[2],pl[2]);
            tsplit(Ps[(w*16+g+8)*68+qf*8+tc+4], ph[3],pl[3]);
            const uint4* wb=(const uint4*)XWf + qf*256 + lane;
#pragma unroll
            for(int n=0;n<8;n++){
                uint4 v=wb[n*32];
                MMAT(sacc[n],ph,v.x,v.z);
                MMAT(sacc[n],ph,v.y,v.w);
                MMAT(sacc[n],pl,v.x,v.z);
            }
        }
#pragma unroll
        for(int qk=0;qk<4;qk++){
            u32 Sh[4],Sl[4];
#pragma unroll
            for(int qq=0;qq<2;qq++){
                const int n=2*qk+qq;
                const int kc=kt*64+n*8+2*tc;
                const float b0v=bas[kc], b1v=bas[kc+1];
                float s0=tanhf_(sacc[n][0]+rv0*b0v);
                float s1=tanhf_(sacc[n][1]+rv0*b1v);
                float s2=tanhf_(sacc[n][2]+rv1*b0v);
                float s3=tanhf_(sacc[n][3]+rv1*b1v);
                Sh[2*qq]  =cvt2(s1,s0); Sl[2*qq]  =cvt2(s1-bfhi(Sh[2*qq]),  s0-bflo(Sh[2*qq]));
                Sh[2*qq+1]=cvt2(s3,s2); Sl[2*qq+1]=cvt2(s3-bfhi(Sh[2*qq+1]),s2-bflo(Sh[2*qq+1]));
            }
            const uint4* tb=(const uint4*)XTf + qk*256 + lane;
#pragma unroll
            for(int n=0;n<8;n++){
                uint4 v=tb[n*32];
                MMAB(hacc[n],Sh,v.x,v.y);
                MMAB(hacc[n],Sh,v.z,v.w);
                MMAB(hacc[n],Sl,v.x,v.y);
            }
        }
        __syncthreads();
    }

    // ---- epilogue ----
    {
        const int il=i0+w*16+g, ih=il+8;
#pragma unroll
        for(int n=0;n<8;n++){
            const int d=n*8+2*tc;
            float2 v0, v1;
            v0.x=hacc[n][0]+bW[d]; v0.y=hacc[n][1]+bW[d+1];
            v1.x=hacc[n][2]+bW[d]; v1.y=hacc[n][3]+bW[d+1];
            *(float2*)&H[((size_t)b*NN+il)*NF+d]=v0;
            *(float2*)&H[((size_t)b*NN+ih)*NF+d]=v1;
        }
    }
}

// ---------------------------------------------------------------------------
extern "C" void kernel_launch(void* const* d_in, const int* in_sizes, int n_in,
                              void* d_out, int out_size){
    const float* X =(const float*)d_in[0];
    const float* A =(const float*)d_in[1];
    const int*   N =(const int*)d_in[2];
    const float* W =(const float*)d_in[3];
    const float* a =(const float*)d_in[4];
    const float* bW=(const float*)d_in[5];
    const float* ba=(const float*)d_in[6];
    float* H=(float*)d_out;
    cudaFuncSetAttribute(k_main, cudaFuncAttributeMaxDynamicSharedMemorySize, SMEMB);
    k_colsum<<<1,64>>>(a,N);
    k_prep<<<NB*8,256>>>(X,W);
    k_main<<<dim3(4,NB),256,SMEMB>>>(A,ba,bW,H);
}